// round 15
// baseline (speedup 1.0000x reference)
#include <cuda_runtime.h>
#include <math.h>

#define TT  100
#define HH  50
#define ZZ  10
#define OUTD 65          // ZZ + ZZ*(ZZ+1)/2
#define NTRI 55          // ZZ*(ZZ+1)/2
#define LN_EPS 1e-6f
#define NTHREADS 96

// scratch for hs (T x H) + progress flag — __device__ globals, no allocation
__device__ float g_hs[TT * HH];
__device__ int   g_prog;          // monotone step counter (chunked)

__device__ __forceinline__ float fast_sigmoid(float x) {
    float e = __expf(-x);
    return __fdividef(1.0f, 1.0f + e);
}
__device__ __forceinline__ float fast_tanh(float x) {
    float e = __expf(-2.0f * fabsf(x));
    float t = __fdividef(1.0f - e, 1.0f + e);
    return copysignf(t, x);
}

// ---------------------------------------------------------------------------
// Recurrence (CTA 0): R2/R6-proven one-barrier design. 3 warps, warp g owns
// gate g. Lane l owns columns 2l, 2l+1 (active l < 25); weights in float2
// registers; h in registers, broadcast by SHFL; ONE __syncthreads per step
// with parity-double-buffered gate exchange. g_hs stores split across warps.
// Progress published every 10 steps (tid0 fence + flag).
// ---------------------------------------------------------------------------
__device__ __forceinline__ void recurrence_body(
    const float* __restrict__ carry_init,
    const float* __restrict__ W_hr, const float* __restrict__ b_hr,
    const float* __restrict__ s_r,  const float* __restrict__ o_r,
    const float* __restrict__ W_hz, const float* __restrict__ b_hz,
    const float* __restrict__ s_z,  const float* __restrict__ o_z,
    const float* __restrict__ W_hn, const float* __restrict__ b_hn,
    const float* __restrict__ s_n,  const float* __restrict__ o_n)
{
    __shared__ float gate_sh[2][3][64];   // [parity][gate][col] (padded rows)

    const int tid  = threadIdx.x;
    const int g    = tid >> 5;            // warp = gate, 0..2
    const int l    = tid & 31;            // lane
    const bool act = (l < 25);
    const int c0   = act ? 2 * l : 0;     // clamped for inactive lanes
    // g_hs store ownership: warp0 -> pairs 0-8, warp1 -> 9-16, warp2 -> 17-24
    const int owner = (l < 9) ? 0 : (l < 17) ? 1 : 2;

    const float* Wg = (g == 0) ? W_hr : (g == 1) ? W_hz : W_hn;
    const float* bg = (g == 0) ? b_hr : (g == 1) ? b_hz : b_hn;
    const float* sg = (g == 0) ? s_r  : (g == 1) ? s_z  : s_n;
    const float* og = (g == 0) ? o_r  : (g == 1) ? o_z  : o_n;

    // per-lane weight columns in registers: w[i] = (W[i][c0], W[i][c0+1])
    float2 w[HH];
    #pragma unroll
    for (int i = 0; i < HH; i++)
        w[i] = *reinterpret_cast<const float2*>(Wg + i * HH + c0);

    const float b0 = bg[c0], b1 = bg[c0 + 1];
    const float sc0 = sg[c0], sc1 = sg[c0 + 1];
    const float of0 = og[c0], of1 = og[c0 + 1];

    // h state in registers (lane l holds h[2l], h[2l+1])
    float h0 = carry_init[c0];
    float h1 = carry_init[c0 + 1];

    for (int t = 0; t < TT; t++) {
        // ---- matvec: acc = b + sum_i h[i] * W[i][c0..c0+1]
        float2 a[4];
        a[0] = make_float2(b0, b1);
        a[1] = make_float2(0.f, 0.f);
        a[2] = make_float2(0.f, 0.f);
        a[3] = make_float2(0.f, 0.f);
        #pragma unroll
        for (int i = 0; i < HH; i++) {
            float hv = __shfl_sync(0xffffffffu, (i & 1) ? h1 : h0, i >> 1);
            a[i & 3].x = fmaf(hv, w[i].x, a[i & 3].x);
            a[i & 3].y = fmaf(hv, w[i].y, a[i & 3].y);
        }
        float px = (a[0].x + a[1].x) + (a[2].x + a[3].x);
        float py = (a[0].y + a[1].y) + (a[2].y + a[3].y);

        // ---- in-warp layernorm stats over this gate's 50 columns
        float sv = 0.f, qv = 0.f;
        if (act) { sv = px + py; qv = px * px + py * py; }
        #pragma unroll
        for (int off = 16; off; off >>= 1) {
            sv += __shfl_xor_sync(0xffffffffu, sv, off);
            qv += __shfl_xor_sync(0xffffffffu, qv, off);
        }
        float mean = sv * (1.0f / HH);
        float var  = qv * (1.0f / HH) - mean * mean;
        float inv  = rsqrtf(var + LN_EPS);

        float nx = (px - mean) * inv * sc0 + of0;
        float ny = (py - mean) * inv * sc1 + of1;

        float gx, gy;
        if (g < 2) { gx = fast_sigmoid(nx); gy = fast_sigmoid(ny); }
        else       { gx = nx;               gy = ny;               }

        const int buf = t & 1;
        if (act)
            *reinterpret_cast<float2*>(&gate_sh[buf][g][c0]) = make_float2(gx, gy);
        __syncthreads();                       // the ONE barrier per step

        // publish progress for steps < t (their STGs precede this barrier)
        if (tid == 0 && t > 0 && (t % 10) == 0) {
            __threadfence();
            *(volatile int*)&g_prog = t;       // steps 0..t-1 ready
        }

        // ---- combine gates; every warp redundantly updates its h registers
        if (act) {
            float2 rv = *reinterpret_cast<float2*>(&gate_sh[buf][0][c0]);
            float2 zv = *reinterpret_cast<float2*>(&gate_sh[buf][1][c0]);
            float2 lv = *reinterpret_cast<float2*>(&gate_sh[buf][2][c0]);
            float n0 = fast_tanh(rv.x * lv.x);
            float n1 = fast_tanh(rv.y * lv.y);
            h0 = zv.x * (h0 - n0) + n0;        // (1-z)*n + z*h
            h1 = zv.y * (h1 - n1) + n1;
            if (g == owner)                    // split STG issue across warps
                *reinterpret_cast<float2*>(&g_hs[t * HH + c0]) = make_float2(h0, h1);
        }
    }

    __syncthreads();                           // all warps issued final STGs
    if (tid == 0) {
        __threadfence();
        *(volatile int*)&g_prog = TT;          // all steps ready
    }
}

// ---------------------------------------------------------------------------
// nat body (CTAs 1..100): per-timestep epilogue, 96 threads.
// W_dense column + bias prefetched BEFORE the spin-wait.
// ADAPTIVE BACKOFF spin: CTAs far from their deadline sleep 4us per poll so
// the chip isn't dragged down by 100 hot spinners (DVFS); CTAs within ~2
// publish batches poll every ~200ns.
// Output layout (fp32): [Sigma T*Z*Z][mu T*Z][J T*Z*Z][h_nat T*Z]
// ---------------------------------------------------------------------------
__device__ __forceinline__ void nat_body(
    int t,
    const float* __restrict__ W_dense,
    const float* __restrict__ b_dense,
    float* __restrict__ out)
{
    const int tid = threadIdx.x;

    __shared__ float hsh[HH];
    __shared__ float osh[OUTD];
    __shared__ float L   [ZZ][ZZ];
    __shared__ float rdia[ZZ];
    __shared__ float Li  [ZZ][ZZ];
    __shared__ float Jsh [ZZ][ZZ];

    // ---- prefetch (overlaps with the recurrence; off critical path)
    float wcol[HH];
    float bv = 0.f;
    if (tid < OUTD) {
        bv = b_dense[tid];
        #pragma unroll
        for (int i = 0; i < HH; i++)
            wcol[i] = W_dense[i * OUTD + tid];
    }

    // ---- wait until the recurrence has published this timestep.
    // Adaptive backoff: sleep long while far away (power -> clocks), short
    // when close (tail latency).
    if (tid == 0) {
        int p = *(volatile int*)&g_prog;
        while (p < t + 1) {
            __nanosleep((t + 1 - p > 20) ? 4096u : 200u);
            p = *(volatile int*)&g_prog;
        }
        __threadfence();
    }
    __syncthreads();

    if (tid < HH) hsh[tid] = g_hs[t * HH + tid];
    __syncthreads();

    // dense: out[o] = b[o] + sum_i hs[t][i] * W_dense[i][o]
    if (tid < OUTD) {
        float a = bv;
        #pragma unroll
        for (int i = 0; i < HH; i++)
            a = fmaf(hsh[i], wcol[i], a);
        osh[tid] = a;
    }
    __syncthreads();

    // build lower-triangular L from flat part; softplus on diagonal
    if (tid < NTRI) {                               // 55 < 96: single shot OK
        int k = tid;
        int r = (int)((sqrtf(8.0f * k + 1.0f) - 1.0f) * 0.5f);
        int c = k - r * (r + 1) / 2;
        float v = osh[ZZ + k];
        if (c == r) {
            v = fmaxf(v, 0.0f) + log1pf(__expf(-fabsf(v)));
            rdia[r] = __fdividef(1.0f, v);
        }
        L[r][c] = v;
    }
    __syncthreads();

    const int SIG_OFF = 0;
    const int MU_OFF  = TT * ZZ * ZZ;
    const int J_OFF   = MU_OFF + TT * ZZ;
    const int HN_OFF  = J_OFF + TT * ZZ * ZZ;

    // mu
    if (tid < ZZ) out[MU_OFF + t * ZZ + tid] = osh[tid];

    // Sigma = L L^T  (100 entries > 96 threads: stride)
    for (int idx = tid; idx < ZZ * ZZ; idx += NTHREADS) {
        int i = idx / ZZ, jj = idx % ZZ;
        int m = (i < jj) ? i : jj;
        float sacc = 0.f;
        for (int k = 0; k <= m; k++) sacc = fmaf(L[i][k], L[jj][k], sacc);
        out[SIG_OFF + t * ZZ * ZZ + idx] = sacc;
    }

    // L^{-1}: forward substitution, one column per thread (tid = column jc)
    if (tid < ZZ) {
        const int jc = tid;
        float x[ZZ];
        #pragma unroll
        for (int i = 0; i < ZZ; i++) {
            if (i < jc) { x[i] = 0.f; continue; }
            float s2 = (i == jc) ? 1.0f : 0.0f;
            #pragma unroll
            for (int k = 0; k < ZZ; k++)
                if (k >= jc && k < i) s2 -= L[i][k] * x[k];
            x[i] = s2 * rdia[i];
            Li[i][jc] = x[i];
        }
    }
    __syncthreads();

    // J = L^{-T} L^{-1} : J[i][j] = sum_{k>=max(i,j)} Li[k][i]*Li[k][j]
    for (int idx = tid; idx < ZZ * ZZ; idx += NTHREADS) {
        int i = idx / ZZ, jj = idx % ZZ;
        int m = (i > jj) ? i : jj;
        float sacc = 0.f;
        for (int k = m; k < ZZ; k++) sacc = fmaf(Li[k][i], Li[k][jj], sacc);
        Jsh[i][jj] = sacc;
        out[J_OFF + t * ZZ * ZZ + idx] = sacc;
    }
    __syncthreads();

    // h_nat = J @ mu
    if (tid < ZZ) {
        float sacc = 0.f;
        #pragma unroll
        for (int jj = 0; jj < ZZ; jj++)
            sacc = fmaf(Jsh[tid][jj], osh[jj], sacc);
        out[HN_OFF + t * ZZ + tid] = sacc;
    }
}

// ---------------------------------------------------------------------------
// Fused kernel: CTA 0 = recurrence producer; CTAs 1..100 = nat consumers.
// All 101 CTAs are co-resident (<= 148 SMs), so the spin-wait cannot deadlock.
// ---------------------------------------------------------------------------
__global__ void __launch_bounds__(NTHREADS, 1) gru_fused_kernel(
    const float* __restrict__ carry_init,
    const float* __restrict__ W_hr, const float* __restrict__ b_hr,
    const float* __restrict__ s_r,  const float* __restrict__ o_r,
    const float* __restrict__ W_hz, const float* __restrict__ b_hz,
    const float* __restrict__ s_z,  const float* __restrict__ o_z,
    const float* __restrict__ W_hn, const float* __restrict__ b_hn,
    const float* __restrict__ s_n,  const float* __restrict__ o_n,
    const float* __restrict__ W_dense,
    const float* __restrict__ b_dense,
    float* __restrict__ out)
{
    if (blockIdx.x == 0) {
        recurrence_body(carry_init,
                        W_hr, b_hr, s_r, o_r,
                        W_hz, b_hz, s_z, o_z,
                        W_hn, b_hn, s_n, o_n);
    } else {
        nat_body(blockIdx.x - 1, W_dense, b_dense, out);
    }
}

// ---------------------------------------------------------------------------
// Launch. Input order (metadata): carry_init, W_hr, b_hr, s_r, o_r,
// W_hz, b_hz, s_z, o_z, W_hn, b_hn, s_n, o_n, W_dense, b_dense
// ---------------------------------------------------------------------------
extern "C" void kernel_launch(void* const* d_in, const int* in_sizes, int n_in,
                              void* d_out, int out_size)
{
    const float* carry   = (const float*)d_in[0];
    const float* W_hr    = (const float*)d_in[1];
    const float* b_hr    = (const float*)d_in[2];
    const float* s_r     = (const float*)d_in[3];
    const float* o_r     = (const float*)d_in[4];
    const float* W_hz    = (const float*)d_in[5];
    const float* b_hz    = (const float*)d_in[6];
    const float* s_z     = (const float*)d_in[7];
    const float* o_z     = (const float*)d_in[8];
    const float* W_hn    = (const float*)d_in[9];
    const float* b_hn    = (const float*)d_in[10];
    const float* s_n     = (const float*)d_in[11];
    const float* o_n     = (const float*)d_in[12];
    const float* W_dense = (const float*)d_in[13];
    const float* b_dense = (const float*)d_in[14];

    gru_fused_kernel<<<1 + TT, NTHREADS>>>(carry,
        W_hr, b_hr, s_r, o_r,
        W_hz, b_hz, s_z, o_z,
        W_hn, b_hn, s_n, o_n,
        W_dense, b_dense, (float*)d_out);
}